// round 2
// baseline (speedup 1.0000x reference)
#include <cuda_runtime.h>
#include <cstdint>

#define BB     4
#define SS     2048
#define DM     1024
#define HH     16
#define DK     64
#define MTOT   (BB*SS)          // 8192

// ---------------- scratch (device globals; allocation-free) ----------------
__device__ float g_Q[BB*HH*SS*DK];   // (b,h,s,d)
__device__ float g_K[BB*HH*SS*DK];
__device__ float g_V[BB*HH*SS*DK];
__device__ float g_A[BB*SS*DM];      // attention output, (b,s,D)

// ---------------- GEMM: C[M,N] = A[M,K] @ W[N,K]^T + bias ----------------
// 128x128x16 tiles, 256 threads, 8x8 microtile.
// MODE 0: C[m*N+n].  MODE 1: split-heads write into (b,h,s,d) scratch.
template<int MODE>
__global__ __launch_bounds__(256)
void gemm_nt(const float* __restrict__ A, const float* __restrict__ W,
             const float* __restrict__ bias, float* __restrict__ C,
             int M, int N, int K)
{
    __shared__ float As[16][132];
    __shared__ float Bs[16][132];

    const int t  = threadIdx.x;
    const int tx = t & 15;
    const int ty = t >> 4;
    const int rowBase = blockIdx.y * 128;
    const int colBase = blockIdx.x * 128;

    float acc[8][8];
#pragma unroll
    for (int i = 0; i < 8; i++)
#pragma unroll
        for (int j = 0; j < 8; j++) acc[i][j] = 0.f;

    for (int kb = 0; kb < K; kb += 16) {
#pragma unroll
        for (int p = 0; p < 2; p++) {
            int f  = t + p * 256;          // 0..511
            int r  = f >> 2;               // 0..127
            int kq = f & 3;                // 0..3  (4 k-values each)
            float4 av = *(const float4*)(A + (size_t)(rowBase + r) * K + kb + kq * 4);
            As[kq*4+0][r] = av.x; As[kq*4+1][r] = av.y;
            As[kq*4+2][r] = av.z; As[kq*4+3][r] = av.w;
            float4 bv = *(const float4*)(W + (size_t)(colBase + r) * K + kb + kq * 4);
            Bs[kq*4+0][r] = bv.x; Bs[kq*4+1][r] = bv.y;
            Bs[kq*4+2][r] = bv.z; Bs[kq*4+3][r] = bv.w;
        }
        __syncthreads();
#pragma unroll
        for (int kk = 0; kk < 16; kk++) {
            float a[8], b[8];
            float4 a0 = *(const float4*)&As[kk][ty*8];
            float4 a1 = *(const float4*)&As[kk][ty*8+4];
            float4 b0 = *(const float4*)&Bs[kk][tx*8];
            float4 b1 = *(const float4*)&Bs[kk][tx*8+4];
            a[0]=a0.x; a[1]=a0.y; a[2]=a0.z; a[3]=a0.w;
            a[4]=a1.x; a[5]=a1.y; a[6]=a1.z; a[7]=a1.w;
            b[0]=b0.x; b[1]=b0.y; b[2]=b0.z; b[3]=b0.w;
            b[4]=b1.x; b[5]=b1.y; b[6]=b1.z; b[7]=b1.w;
#pragma unroll
            for (int i = 0; i < 8; i++)
#pragma unroll
                for (int j = 0; j < 8; j++)
                    acc[i][j] = fmaf(a[i], b[j], acc[i][j]);
        }
        __syncthreads();
    }

#pragma unroll
    for (int i = 0; i < 8; i++) {
        int m = rowBase + ty*8 + i;
#pragma unroll
        for (int j = 0; j < 8; j++) {
            int n = colBase + tx*8 + j;
            float v = acc[i][j] + bias[n];
            if (MODE == 0) {
                C[(size_t)m * N + n] = v;
            } else {
                int b = m >> 11;         // m / S
                int s = m & 2047;        // m % S
                int h = n >> 6;          // n / 64
                int d = n & 63;          // n % 64
                C[(((size_t)(b * HH + h) << 11) + s) * DK + d] = v;
            }
        }
    }
}

// ---------------- Flash attention (fp32, online softmax) ----------------
// Grid: (S/64, H, B). 256 threads. 64 queries x 64 keys per step, d=64.
// Dynamic smem: Qs[64][68] (row,d), KsT[64][68] (d,col; reused as P[row][col]),
// Vs[64][68] (k,d).
#define APAD 68
#define ATT_SMEM (3 * 64 * APAD * 4)

__global__ __launch_bounds__(256)
void attn_kernel(const int* __restrict__ mask)
{
    extern __shared__ float sm[];
    float* Qs  = sm;
    float* KsT = sm + 64 * APAD;   // also reused as P (prob) tile [row][col]
    float* Vs  = sm + 2 * 64 * APAD;
    __shared__ float rowm[64], rowl[64], rowfac[64];

    const int qt = blockIdx.x, h = blockIdx.y, b = blockIdx.z;
    const int t  = threadIdx.x;
    const int tx = t & 15;
    const int ty = t >> 4;

    const float* qptr = g_Q + ((size_t)(b * HH + h) * SS + qt * 64) * DK;
    const float* kbas = g_K + (size_t)(b * HH + h) * SS * DK;
    const float* vbas = g_V + (size_t)(b * HH + h) * SS * DK;
    const int*   mrow = mask + b * SS;

    // load Q tile, pre-scaled by 1/sqrt(dk)
#pragma unroll
    for (int p = 0; p < 4; p++) {
        int f = t + p * 256;            // 0..1023 float4s
        int r = f >> 4, dq = f & 15;
        float4 v = *(const float4*)(qptr + r * DK + dq * 4);
        float* dst = Qs + r * APAD + dq * 4;
        dst[0] = v.x * 0.125f; dst[1] = v.y * 0.125f;
        dst[2] = v.z * 0.125f; dst[3] = v.w * 0.125f;
    }
    if (t < 64) { rowm[t] = -1e30f; rowl[t] = 0.f; }

    float acc[4][4];
#pragma unroll
    for (int i = 0; i < 4; i++)
#pragma unroll
        for (int j = 0; j < 4; j++) acc[i][j] = 0.f;
    __syncthreads();

    for (int kt = 0; kt < SS / 64; kt++) {
        const float* kp = kbas + (size_t)kt * 64 * DK;
        const float* vp = vbas + (size_t)kt * 64 * DK;
#pragma unroll
        for (int p = 0; p < 4; p++) {
            int f = t + p * 256;
            int r = f >> 4, dq = f & 15;
            float4 kv = *(const float4*)(kp + r * DK + dq * 4);
            KsT[(dq*4+0) * APAD + r] = kv.x;
            KsT[(dq*4+1) * APAD + r] = kv.y;
            KsT[(dq*4+2) * APAD + r] = kv.z;
            KsT[(dq*4+3) * APAD + r] = kv.w;
            float4 vv = *(const float4*)(vp + r * DK + dq * 4);
            float* vd = Vs + r * APAD + dq * 4;
            vd[0] = vv.x; vd[1] = vv.y; vd[2] = vv.z; vd[3] = vv.w;
        }
        __syncthreads();

        // S = (Q * 1/8) @ K^T : 4x4 microtile, rows ty*4+i, cols tx*4+j
        float s[4][4];
#pragma unroll
        for (int i = 0; i < 4; i++)
#pragma unroll
            for (int j = 0; j < 4; j++) s[i][j] = 0.f;
#pragma unroll 8
        for (int d = 0; d < 64; d++) {
            float qv[4], kv[4];
#pragma unroll
            for (int i = 0; i < 4; i++) qv[i] = Qs[(ty*4+i) * APAD + d];
#pragma unroll
            for (int j = 0; j < 4; j++) kv[j] = KsT[d * APAD + tx*4+j];
#pragma unroll
            for (int i = 0; i < 4; i++)
#pragma unroll
                for (int j = 0; j < 4; j++)
                    s[i][j] = fmaf(qv[i], kv[j], s[i][j]);
        }
        // mask
#pragma unroll
        for (int j = 0; j < 4; j++) {
            if (mrow[kt * 64 + tx*4 + j] == 0) {
#pragma unroll
                for (int i = 0; i < 4; i++) s[i][j] = -1e9f;
            }
        }
        __syncthreads();   // everyone done reading KsT before reuse as P
#pragma unroll
        for (int i = 0; i < 4; i++)
#pragma unroll
            for (int j = 0; j < 4; j++)
                KsT[(ty*4+i) * APAD + tx*4+j] = s[i][j];
        __syncthreads();

        // online softmax: quad of 4 threads per row
        {
            int r = t >> 2, sub = t & 3;
            float mx = -1e30f;
#pragma unroll
            for (int c = sub; c < 64; c += 4) mx = fmaxf(mx, KsT[r * APAD + c]);
            mx = fmaxf(mx, __shfl_xor_sync(0xffffffffu, mx, 1));
            mx = fmaxf(mx, __shfl_xor_sync(0xffffffffu, mx, 2));
            float mold = rowm[r];
            float mnew = fmaxf(mold, mx);
            float fac  = __expf(mold - mnew);
            float psum = 0.f;
#pragma unroll
            for (int c = sub; c < 64; c += 4) {
                float pv = __expf(KsT[r * APAD + c] - mnew);
                KsT[r * APAD + c] = pv;
                psum += pv;
            }
            psum += __shfl_xor_sync(0xffffffffu, psum, 1);
            psum += __shfl_xor_sync(0xffffffffu, psum, 2);
            if (sub == 0) {
                rowm[r]   = mnew;
                rowl[r]   = rowl[r] * fac + psum;
                rowfac[r] = fac;
            }
        }
        __syncthreads();

        // rescale and accumulate O += P @ V
        float fc[4];
#pragma unroll
        for (int i = 0; i < 4; i++) fc[i] = rowfac[ty*4+i];
#pragma unroll
        for (int i = 0; i < 4; i++)
#pragma unroll
            for (int j = 0; j < 4; j++) acc[i][j] *= fc[i];
#pragma unroll 8
        for (int k = 0; k < 64; k++) {
            float pv[4], vv[4];
#pragma unroll
            for (int i = 0; i < 4; i++) pv[i] = KsT[(ty*4+i) * APAD + k];
#pragma unroll
            for (int j = 0; j < 4; j++) vv[j] = Vs[k * APAD + tx*4+j];
#pragma unroll
            for (int i = 0; i < 4; i++)
#pragma unroll
                for (int j = 0; j < 4; j++)
                    acc[i][j] = fmaf(pv[i], vv[j], acc[i][j]);
        }
        __syncthreads();
    }

    // normalize and write to (b, s, h*64+d)
#pragma unroll
    for (int i = 0; i < 4; i++) {
        int qr = ty*4 + i;
        float inv = 1.0f / rowl[qr];
        size_t base = ((size_t)b * SS + qt * 64 + qr) * DM + h * DK;
#pragma unroll
        for (int j = 0; j < 4; j++)
            g_A[base + tx*4 + j] = acc[i][j] * inv;
    }
}

// ---------------- launch ----------------
extern "C" void kernel_launch(void* const* d_in, const int* in_sizes, int n_in,
                              void* d_out, int out_size)
{
    const float* query = (const float*)d_in[0];
    const float* key   = (const float*)d_in[1];
    const float* value = (const float*)d_in[2];
    const int*   mask  = (const int*)  d_in[3];
    const float* Wq = (const float*)d_in[4];
    const float* bq = (const float*)d_in[5];
    const float* Wk = (const float*)d_in[6];
    const float* bk = (const float*)d_in[7];
    const float* Wv = (const float*)d_in[8];
    const float* bv = (const float*)d_in[9];
    const float* Wo = (const float*)d_in[10];
    const float* bo = (const float*)d_in[11];
    float* out = (float*)d_out;

    float *pQ, *pK, *pV, *pA;
    cudaGetSymbolAddress((void**)&pQ, g_Q);
    cudaGetSymbolAddress((void**)&pK, g_K);
    cudaGetSymbolAddress((void**)&pV, g_V);
    cudaGetSymbolAddress((void**)&pA, g_A);

    cudaFuncSetAttribute(attn_kernel, cudaFuncAttributeMaxDynamicSharedMemorySize,
                         ATT_SMEM);

    dim3 gGemm(DM / 128, MTOT / 128);   // (8, 64)
    gemm_nt<1><<<gGemm, 256>>>(query, Wq, bq, pQ, MTOT, DM, DM);
    gemm_nt<1><<<gGemm, 256>>>(key,   Wk, bk, pK, MTOT, DM, DM);
    gemm_nt<1><<<gGemm, 256>>>(value, Wv, bv, pV, MTOT, DM, DM);

    dim3 gAttn(SS / 64, HH, BB);        // (32, 16, 4)
    attn_kernel<<<gAttn, 256, ATT_SMEM>>>(mask);

    gemm_nt<0><<<gGemm, 256>>>(pA, Wo, bo, out, MTOT, DM, DM);
}

// round 5
// speedup vs baseline: 1.4688x; 1.4688x over previous
#include <cuda_runtime.h>
#include <cstdint>

#define BB     4
#define SS     2048
#define DM     1024
#define HH     16
#define DK     64
#define MTOT   (BB*SS)          // 8192

// ---------------- scratch (device globals; allocation-free) ----------------
__device__ float g_Q[BB*HH*SS*DK];   // (b,h,s,d)
__device__ float g_K[BB*HH*SS*DK];
__device__ float g_V[BB*HH*SS*DK];
__device__ float g_A[BB*SS*DM];      // attention output, (b,s,D)

// ======================= PTX helpers =======================
__device__ __forceinline__ uint32_t smem_u32(const void* p) {
    uint32_t a;
    asm("{ .reg .u64 t; cvta.to.shared.u64 t, %1; cvt.u32.u64 %0, t; }"
        : "=r"(a) : "l"(p));
    return a;
}

__device__ __forceinline__ uint32_t f2tf32(float x) {
    uint32_t r;
    asm("cvt.rna.tf32.f32 %0, %1;" : "=r"(r) : "f"(x));
    return r;
}

#define CP_ASYNC16(dst, src) \
    asm volatile("cp.async.cg.shared.global [%0], [%1], 16;" \
                 :: "r"(dst), "l"(src))
#define CP_COMMIT() asm volatile("cp.async.commit_group;" ::: "memory")
#define CP_WAIT1()  asm volatile("cp.async.wait_group 1;" ::: "memory")
#define CP_WAIT0()  asm volatile("cp.async.wait_group 0;" ::: "memory")

__device__ __forceinline__ void mma_tf32(float& c0, float& c1, float& c2, float& c3,
                                         uint32_t a0, uint32_t a1, uint32_t a2, uint32_t a3,
                                         uint32_t b0, uint32_t b1) {
    asm volatile(
        "mma.sync.aligned.m16n8k8.row.col.f32.tf32.tf32.f32 "
        "{%0,%1,%2,%3}, {%4,%5,%6,%7}, {%8,%9}, {%0,%1,%2,%3};"
        : "+f"(c0), "+f"(c1), "+f"(c2), "+f"(c3)
        : "r"(a0), "r"(a1), "r"(a2), "r"(a3), "r"(b0), "r"(b1));
}

// ================= mma.sync tf32 GEMM: C = A[M,1024] @ W[N,1024]^T + b =======
// 128x128x32 tile, 256 threads (8 warps = 2m x 4n), warp tile 64x32.
// Fragments: 4 m-tiles (m16) x 4 n-tiles (n8) per warp, k8 steps.
// MODE 0: C[m*1024+n]. MODE 1: split-heads (b,h,s,d).
#define KC    32
#define GPAD  36        // floats per smem row (pad: bank = (4*row+k)%32 = lane)
#define NCHUNK (DM / KC)    // 32
#define STAGE_FLOATS (2 * 128 * GPAD)          // A + B per stage
#define GSM_TOTAL (2 * STAGE_FLOATS * 4)       // bytes, 2 stages = 73728

template<int MODE>
__global__ __launch_bounds__(256)
void gemm_mma(const float* __restrict__ A, const float* __restrict__ W,
              const float* __restrict__ bias, float* __restrict__ C)
{
    extern __shared__ float sm[];
    __shared__ float bias_s[128];

    const int t    = threadIdx.x;
    const int lane = t & 31;
    const int w    = t >> 5;               // 0..7
    const int wm   = (w >> 2) * 64;        // warp m offset: 0 or 64
    const int wn   = (w & 3) * 32;         // warp n offset: 0,32,64,96
    const int rowBase = blockIdx.y * 128;
    const int colBase = blockIdx.x * 128;

    const uint32_t smb = smem_u32(sm);

    if (t < 128) bias_s[t] = bias[colBase + t];

    float acc[4][4][4];
#pragma unroll
    for (int mi = 0; mi < 4; mi++)
#pragma unroll
        for (int ni = 0; ni < 4; ni++)
#pragma unroll
            for (int q = 0; q < 4; q++) acc[mi][ni][q] = 0.f;

    const float* Arow = A + (size_t)rowBase * DM;
    const float* Wrow = W + (size_t)colBase * DM;

    // prefetch helper (inlined twice): stage s, k-offset kb
    auto prefetch = [&](int s, int kb) {
        uint32_t Ad = smb + (uint32_t)(s * STAGE_FLOATS) * 4;
        uint32_t Bd = Ad + 128 * GPAD * 4;
#pragma unroll
        for (int p = 0; p < 4; p++) {
            int f = t + p * 256;           // 0..1023
            int r = f >> 3, q = f & 7;     // row 0..127, float4 idx 0..7
            CP_ASYNC16(Ad + (uint32_t)(r * GPAD + q * 4) * 4,
                       Arow + (size_t)r * DM + kb + q * 4);
            CP_ASYNC16(Bd + (uint32_t)(r * GPAD + q * 4) * 4,
                       Wrow + (size_t)r * DM + kb + q * 4);
        }
    };

    prefetch(0, 0);
    CP_COMMIT();

    for (int kc = 0; kc < NCHUNK; kc++) {
        if (kc + 1 < NCHUNK) {
            prefetch((kc + 1) & 1, (kc + 1) * KC);
            CP_COMMIT();
            CP_WAIT1();
        } else {
            CP_WAIT0();
        }
        __syncthreads();

        const float* As = sm + (kc & 1) * STAGE_FLOATS;
        const float* Bs = As + 128 * GPAD;
        const int lk = lane & 3;           // fragment k sub-index
        const int lr = lane >> 2;          // fragment row/col sub-index

#pragma unroll
        for (int kk = 0; kk < 4; kk++) {
            const int k0 = kk * 8 + lk;
            uint32_t af[4][4], bf[4][2];
#pragma unroll
            for (int mi = 0; mi < 4; mi++) {
                const float* ap = As + (wm + mi * 16 + lr) * GPAD + k0;
                af[mi][0] = f2tf32(ap[0]);
                af[mi][1] = f2tf32(ap[8 * GPAD]);
                af[mi][2] = f2tf32(ap[4]);
                af[mi][3] = f2tf32(ap[8 * GPAD + 4]);
            }
#pragma unroll
            for (int ni = 0; ni < 4; ni++) {
                const float* bp = Bs + (wn + ni * 8 + lr) * GPAD + k0;
                bf[ni][0] = f2tf32(bp[0]);
                bf[ni][1] = f2tf32(bp[4]);
            }
#pragma unroll
            for (int mi = 0; mi < 4; mi++)
#pragma unroll
                for (int ni = 0; ni < 4; ni++)
                    mma_tf32(acc[mi][ni][0], acc[mi][ni][1],
                             acc[mi][ni][2], acc[mi][ni][3],
                             af[mi][0], af[mi][1], af[mi][2], af[mi][3],
                             bf[ni][0], bf[ni][1]);
        }
        __syncthreads();
    }

    // epilogue: c0,c1 -> (row, col..col+1); c2,c3 -> (row+8, col..col+1)
    const int lr = lane >> 2, lc = (lane & 3) * 2;
#pragma unroll
    for (int mi = 0; mi < 4; mi++) {
#pragma unroll
        for (int ni = 0; ni < 4; ni++) {
            const int cl = wn + ni * 8 + lc;       // local col (even)
            const int n  = colBase + cl;
            const float bz0 = bias_s[cl], bz1 = bias_s[cl + 1];
#pragma unroll
            for (int half = 0; half < 2; half++) {
                const int m = rowBase + wm + mi * 16 + lr + half * 8;
                float2 v;
                v.x = acc[mi][ni][half * 2 + 0] + bz0;
                v.y = acc[mi][ni][half * 2 + 1] + bz1;
                if (MODE == 0) {
                    *(float2*)(C + (size_t)m * DM + n) = v;
                } else {
                    int b = m >> 11, s = m & 2047;
                    int h = n >> 6,  d = n & 63;
                    *(float2*)(C + (((size_t)(b * HH + h) << 11) + s) * DK + d) = v;
                }
            }
        }
    }
}

// ---------------- Flash attention (fp32, online softmax) — unchanged --------
#define APAD 68
#define ATT_SMEM (3 * 64 * APAD * 4)

__global__ __launch_bounds__(256)
void attn_kernel(const int* __restrict__ mask)
{
    extern __shared__ float smf[];
    float* Qs  = smf;
    float* KsT = smf + 64 * APAD;
    float* Vs  = smf + 2 * 64 * APAD;
    __shared__ float rowm[64], rowl[64], rowfac[64];

    const int qt = blockIdx.x, h = blockIdx.y, b = blockIdx.z;
    const int t  = threadIdx.x;
    const int tx = t & 15;
    const int ty = t >> 4;

    const float* qptr = g_Q + ((size_t)(b * HH + h) * SS + qt * 64) * DK;
    const float* kbas = g_K + (size_t)(b * HH + h) * SS * DK;
    const float* vbas = g_V + (size_t)(b * HH + h) * SS * DK;
    const int*   mrow = mask + b * SS;

#pragma unroll
    for (int p = 0; p < 4; p++) {
        int f = t + p * 256;
        int r = f >> 4, dq = f & 15;
        float4 v = *(const float4*)(qptr + r * DK + dq * 4);
        float* dst = Qs + r * APAD + dq * 4;
        dst[0] = v.x * 0.125f; dst[1] = v.y * 0.125f;
        dst[2] = v.z * 0.125f; dst[3] = v.w * 0.125f;
    }
    if (t < 64) { rowm[t] = -1e30f; rowl[t] = 0.f; }

    float acc[4][4];
#pragma unroll
    for (int i = 0; i < 4; i++)
#pragma unroll
        for (int j = 0; j < 4; j++) acc[i][j] = 0.f;
    __syncthreads();

    for (int kt = 0; kt < SS / 64; kt++) {
        const float* kp = kbas + (size_t)kt * 64 * DK;
        const float* vp = vbas + (size_t)kt * 64 * DK;
#pragma unroll
        for (int p = 0; p < 4; p++) {
            int f = t + p * 256;
            int r = f >> 4, dq = f & 15;
            float4 kv = *(const float4*)(kp + r * DK + dq * 4);
            KsT[(dq*4+0) * APAD + r] = kv.x;
            KsT[(dq*4+1) * APAD + r] = kv.y;
            KsT[(dq*4+2) * APAD + r] = kv.z;
            KsT[(dq*4+3) * APAD + r] = kv.w;
            float4 vv = *(const float4*)(vp + r * DK + dq * 4);
            float* vd = Vs + r * APAD + dq * 4;
            vd[0] = vv.x; vd[1] = vv.y; vd[2] = vv.z; vd[3] = vv.w;
        }
        __syncthreads();

        float s[4][4];
#pragma unroll
        for (int i = 0; i < 4; i++)
#pragma unroll
            for (int j = 0; j < 4; j++) s[i][j] = 0.f;
#pragma unroll 8
        for (int d = 0; d < 64; d++) {
            float qv[4], kv[4];
#pragma unroll
            for (int i = 0; i < 4; i++) qv[i] = Qs[(ty*4+i) * APAD + d];
#pragma unroll
            for (int j = 0; j < 4; j++) kv[j] = KsT[d * APAD + tx*4+j];
#pragma unroll
            for (int i = 0; i < 4; i++)
#pragma unroll
                for (int j = 0; j < 4; j++)
                    s[i][j] = fmaf(qv[i], kv[j], s[i][j]);
        }
#pragma unroll
        for (int j = 0; j < 4; j++) {
            if (mrow[kt * 64 + tx*4 + j] == 0) {
#pragma unroll
                for (int i = 0; i < 4; i++) s[i][j] = -1e9f;
            }
        }
        __syncthreads();
#pragma unroll
        for (int i = 0; i < 4; i++)
#pragma unroll
            for (int j = 0; j < 4; j++)
                KsT[(ty*4+i) * APAD + tx*4+j] = s[i][j];
        __syncthreads();

        {
            int r = t >> 2, sub = t & 3;
            float mx = -1e30f;
#pragma unroll
            for (int c = sub; c < 64; c += 4) mx = fmaxf(mx, KsT[r * APAD + c]);
            mx = fmaxf(mx, __shfl_xor_sync(0xffffffffu, mx, 1));
            mx = fmaxf(mx, __shfl_xor_sync(0xffffffffu, mx, 2));
            float mold = rowm[r];
            float mnew = fmaxf(mold, mx);
            float fac  = __expf(mold - mnew);
            float psum = 0.f;
#pragma unroll
            for (int c = sub; c < 64; c += 4) {
                float pv = __expf(KsT[r * APAD + c] - mnew);
                KsT[r * APAD + c] = pv;
                psum += pv;
            }
            psum += __shfl_xor_sync(0xffffffffu, psum, 1);
            psum += __shfl_xor_sync(0xffffffffu, psum, 2);
            if (sub == 0) {
                rowm[r]   = mnew;
                rowl[r]   = rowl[r] * fac + psum;
                rowfac[r] = fac;
            }
        }
        __syncthreads();

        float fc[4];
#pragma unroll
        for (int i = 0; i < 4; i++) fc[i] = rowfac[ty*4+i];
#pragma unroll
        for (int i = 0; i < 4; i++)
#pragma unroll
            for (int j = 0; j < 4; j++) acc[i][j] *= fc[i];
#pragma unroll 8
        for (int k = 0; k < 64; k++) {
            float pv[4], vv[4];
#pragma unroll
            for (int i = 0; i < 4; i++) pv[i] = KsT[(ty*4+i) * APAD + k];
#pragma unroll
            for (int j = 0; j < 4; j++) vv[j] = Vs[k * APAD + tx*4+j];
#pragma unroll
            for (int i = 0; i < 4; i++)
#pragma unroll
                for (int j = 0; j < 4; j++)
                    acc[i][j] = fmaf(pv[i], vv[j], acc[i][j]);
        }
        __syncthreads();
    }

#pragma unroll
    for (int i = 0; i < 4; i++) {
        int qr = ty*4 + i;
        float inv = 1.0f / rowl[qr];
        size_t base = ((size_t)b * SS + qt * 64 + qr) * DM + h * DK;
#pragma unroll
        for (int j = 0; j < 4; j++)
            g_A[base + tx*4 + j] = acc[i][j] * inv;
    }
}

// ---------------- launch ----------------
extern "C" void kernel_launch(void* const* d_in, const int* in_sizes, int n_in,
                              void* d_out, int out_size)
{
    const float* query = (const float*)d_in[0];
    const float* key   = (const float*)d_in[1];
    const float* value = (const float*)d_in[2];
    const int*   mask  = (const int*)  d_in[3];
    const float* Wq = (const float*)d_in[4];
    const float* bq = (const float*)d_in[5];
    const float* Wk = (const float*)d_in[6];
    const float* bk = (const float*)d_in[7];
    const float* Wv = (const float*)d_in[8];
    const float* bv = (const float*)d_in[9];
    const float* Wo = (const float*)d_in[10];
    const float* bo = (const float*)d_in[11];
    float* out = (float*)d_out;

    float *pQ, *pK, *pV, *pA;
    cudaGetSymbolAddress((void**)&pQ, g_Q);
    cudaGetSymbolAddress((void**)&pK, g_K);
    cudaGetSymbolAddress((void**)&pV, g_V);
    cudaGetSymbolAddress((void**)&pA, g_A);

    cudaFuncSetAttribute(attn_kernel, cudaFuncAttributeMaxDynamicSharedMemorySize,
                         ATT_SMEM);
    cudaFuncSetAttribute(gemm_mma<0>, cudaFuncAttributeMaxDynamicSharedMemorySize,
                         GSM_TOTAL);
    cudaFuncSetAttribute(gemm_mma<1>, cudaFuncAttributeMaxDynamicSharedMemorySize,
                         GSM_TOTAL);

    dim3 gGemm(DM / 128, MTOT / 128);   // (8, 64)
    gemm_mma<1><<<gGemm, 256, GSM_TOTAL>>>(query, Wq, bq, pQ);
    gemm_mma<1><<<gGemm, 256, GSM_TOTAL>>>(key,   Wk, bk, pK);
    gemm_mma<1><<<gGemm, 256, GSM_TOTAL>>>(value, Wv, bv, pV);

    dim3 gAttn(SS / 64, HH, BB);        // (32, 16, 4)
    attn_kernel<<<gAttn, 256, ATT_SMEM>>>(mask);

    gemm_mma<0><<<gGemm, 256, GSM_TOTAL>>>(pA, Wo, bo, out);
}